// round 2
// baseline (speedup 1.0000x reference)
#include <cuda_runtime.h>
#include <cstdint>

// SpikeFP32Tanh: [N,32] MSB-first 0/1 float pulses of FP32 values ->
// pack to FP32 word, promote to FP64, t = (e^{2v}-1)/(e^{2v}+1) in FP64,
// round to FP32, unpack to [N,32] pulses.
//
// Warp-transposed layout: one warp handles 32 consecutive elements.
//  - Load step j: lane l reads element (base+j)'s pulse l -> one coalesced
//    128B warp load (1 L1tex wavefront per LDG).
//  - __brev(__ballot) packs the 32 MSB-first pulses into the IEEE word;
//    lane j keeps element (base+j)'s word.
//  - Each lane computes one FP64 tanh via the literal reference formula.
//  - Store step j: lane l writes element (base+j)'s pulse l -> coalesced
//    128B warp store. Pulse float synthesized as bit * 0x3F800000.

__global__ void __launch_bounds__(256)
spike_tanh_kernel(const uint32_t* __restrict__ x, uint32_t* __restrict__ out,
                  int n_elems)
{
    const unsigned FULL = 0xFFFFFFFFu;
    int warp_id = (blockIdx.x * blockDim.x + threadIdx.x) >> 5;
    int lane    = threadIdx.x & 31;
    int base    = warp_id * 32;                 // first element of this warp
    if (base >= n_elems) return;                // whole warp exits together

    const uint32_t* __restrict__ xin  = x   + (size_t)base * 32;
    uint32_t*       __restrict__ xout = out + (size_t)base * 32;

    int nvalid = n_elems - base;                // >=1; ==32 on the hot path

    // ---- pack: 32 coalesced loads + ballots; lane j owns element base+j
    unsigned u = 0u;
    #pragma unroll
    for (int j = 0; j < 32; ++j) {
        uint32_t p = (j < nvalid) ? xin[(size_t)j * 32 + lane] : 0u;
        unsigned b = __ballot_sync(FULL, p != 0u);   // bit l = pulse l (MSB-first)
        if (lane == j) u = __brev(b);                // pulse l -> IEEE bit (31-l)
    }

    // ---- FP64 circuit: exact reference formula
    double v64 = (double)__uint_as_float(u);
    double e2x = exp(2.0 * v64);
    double t64 = (e2x - 1.0) / (e2x + 1.0);
    unsigned ru = __float_as_uint((float)t64);

    // ---- unpack: 32 shuffles + coalesced stores
    #pragma unroll
    for (int j = 0; j < 32; ++j) {
        unsigned rj = __shfl_sync(FULL, ru, j);      // element base+j's word
        if (j < nvalid) {
            // pulse l = IEEE bit (31-l); synthesize 0.0f/1.0f bit pattern
            xout[(size_t)j * 32 + lane] = ((rj >> (31 - lane)) & 1u) * 0x3F800000u;
        }
    }
}

extern "C" void kernel_launch(void* const* d_in, const int* in_sizes, int n_in,
                              void* d_out, int out_size)
{
    const uint32_t* x = (const uint32_t*)d_in[0];
    uint32_t* out     = (uint32_t*)d_out;
    int n_elems       = in_sizes[0] / 32;       // 4,194,304 elements

    const int threads = 256;                    // 8 warps -> 256 elements/block
    int warps  = (n_elems + 31) / 32;
    int blocks = (warps + 7) / 8;
    spike_tanh_kernel<<<blocks, threads>>>(x, out, n_elems);
}

// round 3
// speedup vs baseline: 1.0193x; 1.0193x over previous
#include <cuda_runtime.h>
#include <cstdint>

// SpikeFP32Tanh: [N,32] MSB-first 0/1 float pulses of FP32 values ->
// pack to FP32 word, promote to FP64, t = (e^{2v}-1)/(e^{2v}+1) in FP64,
// round to FP32, unpack to [N,32] pulses.
//
// R3 changes vs R2 (234.5us, DRAM 55%):
//  - Phase-split pack: ALL 32 coalesced loads issued first into p[32]
//    (MLP=32/warp), THEN the 32 ballots. R2 interleaved LDG/VOTE -> MLP~1,
//    exposing full DRAM latency per load.
//  - Vectorized stores: 8x STG.128 (+8 SHFL) instead of 32x STG.32 (+32 SHFL).

__global__ void __launch_bounds__(256)
spike_tanh_kernel(const uint32_t* __restrict__ x, uint32_t* __restrict__ out,
                  int n_elems)
{
    const unsigned FULL = 0xFFFFFFFFu;
    const unsigned ONEF = 0x3F800000u;          // 1.0f bit pattern
    int warp_id = (blockIdx.x * blockDim.x + threadIdx.x) >> 5;
    int lane    = threadIdx.x & 31;
    int base    = warp_id * 32;                 // first element of this warp
    if (base >= n_elems) return;                // N % 32 == 0: whole warp exits

    const uint32_t* __restrict__ xin = x + (size_t)base * 32;
    uint4* __restrict__ xout4 = (uint4*)(out + (size_t)base * 32);

    // ---- phase 1: batch all 32 independent coalesced loads (MLP=32)
    uint32_t p[32];
    #pragma unroll
    for (int j = 0; j < 32; ++j)
        p[j] = xin[(size_t)j * 32 + lane];      // row base+j, pulse position lane

    // ---- phase 2: ballots pack each row's 32 pulses; lane j keeps row base+j
    unsigned u = 0u;
    #pragma unroll
    for (int j = 0; j < 32; ++j) {
        unsigned b = __ballot_sync(FULL, p[j] != 0u);  // bit l = pulse l
        if (lane == j) u = __brev(b);                  // pulse l -> IEEE bit 31-l
    }

    // ---- FP64 circuit: exact reference formula
    double v64 = (double)__uint_as_float(u);
    double e2x = exp(2.0 * v64);
    double t64 = (e2x - 1.0) / (e2x + 1.0);
    unsigned ru = __float_as_uint((float)t64);

    // ---- unpack: 8 shuffles + 8 STG.128
    // iter i: lanes 8g..8g+7 write row r = 4i+g; lane's quad q = lane&7
    // covers pulses 4q..4q+3 (IEEE bits 31-4q .. 28-4q).
    int q  = lane & 7;
    int s0 = 31 - 4 * q;
    #pragma unroll
    for (int i = 0; i < 8; ++i) {
        int r = 4 * i + (lane >> 3);
        unsigned rj = __shfl_sync(FULL, ru, r);  // row r's packed word
        uint4 v;
        v.x = ((rj >> (s0    )) & 1u) * ONEF;
        v.y = ((rj >> (s0 - 1)) & 1u) * ONEF;
        v.z = ((rj >> (s0 - 2)) & 1u) * ONEF;
        v.w = ((rj >> (s0 - 3)) & 1u) * ONEF;
        xout4[i * 32 + lane] = v;                // = row r, 16B chunk q
    }
}

extern "C" void kernel_launch(void* const* d_in, const int* in_sizes, int n_in,
                              void* d_out, int out_size)
{
    const uint32_t* x = (const uint32_t*)d_in[0];
    uint32_t* out     = (uint32_t*)d_out;
    int n_elems       = in_sizes[0] / 32;       // 4,194,304 elements

    const int threads = 256;                    // 8 warps -> 256 elements/block
    int warps  = (n_elems + 31) / 32;
    int blocks = (warps + 7) / 8;
    spike_tanh_kernel<<<blocks, threads>>>(x, out, n_elems);
}